// round 3
// baseline (speedup 1.0000x reference)
#include <cuda_runtime.h>
#include <cuda_bf16.h>
#include <cstdint>

// Problem constants
#define B_  32
#define T_  64
#define V_  50257
#define E_  256
#define H_  512
#define G4_ 2048   // 4*H
#define H2_ 1024   // 2*H
#define M_  2048   // T*B

// ---------------- scratch (device globals; no allocation allowed) ----------------
__device__ float g_base[B_ * G4_];       // h_gates + b_ih + b_hh   (b, g)
__device__ float g_xg[M_ * G4_];         // x_gates[t*B+b][g]
__device__ float g_hs[M_ * H_];          // hs[t*B+b][h]
__device__ float g_hid[M_ * H2_];        // hid[t*B+b][k]  (tf32-rounded)

// ---------------- helpers ----------------
__device__ __forceinline__ float tf32r(float x) {
    uint32_t u;
    asm("cvt.rna.tf32.f32 %0, %1;" : "=r"(u) : "f"(x));
    return __uint_as_float(u);
}

__device__ __forceinline__ void mma_tf32(float* d, const float* a, const float* b) {
    asm volatile(
        "mma.sync.aligned.m16n8k8.row.col.f32.tf32.tf32.f32 "
        "{%0,%1,%2,%3}, {%4,%5,%6,%7}, {%8,%9}, {%0,%1,%2,%3};\n"
        : "+f"(d[0]), "+f"(d[1]), "+f"(d[2]), "+f"(d[3])
        : "r"(__float_as_uint(a[0])), "r"(__float_as_uint(a[1])),
          "r"(__float_as_uint(a[2])), "r"(__float_as_uint(a[3])),
          "r"(__float_as_uint(b[0])), "r"(__float_as_uint(b[1])));
}

__device__ __forceinline__ float sigf(float x) {
    return 1.f / (1.f + __expf(-x));
}

// ---------------- K1: base gates = features @ W_hh^T + b_ih + b_hh ----------------
__global__ void base_kernel(const float* __restrict__ feat,
                            const float* __restrict__ W_hh,
                            const float* __restrict__ b_ih,
                            const float* __restrict__ b_hh,
                            float* __restrict__ base) {
    __shared__ float4 f4[H_ / 4];
    int b = blockIdx.x;
    if (threadIdx.x < H_ / 4)
        f4[threadIdx.x] = ((const float4*)(feat + (size_t)b * H_))[threadIdx.x];
    __syncthreads();
    for (int g = threadIdx.x; g < G4_; g += blockDim.x) {
        const float4* w4 = (const float4*)(W_hh + (size_t)g * H_);
        float s = 0.f;
        #pragma unroll 8
        for (int k = 0; k < H_ / 4; k++) {
            float4 w = w4[k], f = f4[k];
            s += w.x * f.x + w.y * f.y + w.z * f.z + w.w * f.w;
        }
        base[b * G4_ + g] = s + b_ih[g] + b_hh[g];
    }
}

// ---------------- generic 128x128x8 SGEMM: C[m][n] = A[m][:].B[n][:] (+bias) ----------------
// If captions != nullptr, A-row m is gathered: emb[tok(m)] with tok from captions.
__global__ __launch_bounds__(256)
void sgemm_tn(const float* __restrict__ A, const float* __restrict__ Bm,
              const float* __restrict__ bias, float* __restrict__ C,
              int M, int N, int K,
              const int* __restrict__ captions, const float* __restrict__ embA,
              int round_tf32) {
    __shared__ float As[8][132];
    __shared__ float Bs[8][132];
    int tid = threadIdx.x;
    int tx = tid & 15, ty = tid >> 4;
    int m0 = blockIdx.y * 128, n0 = blockIdx.x * 128;

    float acc[8][8];
    #pragma unroll
    for (int i = 0; i < 8; i++)
        #pragma unroll
        for (int j = 0; j < 8; j++) acc[i][j] = 0.f;

    int lrow = tid >> 1;       // 0..127
    int lkq  = tid & 1;        // 0..1
    const float* arow;
    if (captions) {
        int m = m0 + lrow;
        int bb = m & 31, tt = m >> 5;
        int ct = (tt == 0) ? 0 : (tt - 1);
        int tok = captions[bb * T_ + ct];
        arow = embA + (size_t)tok * K;
    } else {
        arow = A + (size_t)(m0 + lrow) * K;
    }
    const float* brow = Bm + (size_t)(n0 + lrow) * K;

    for (int k0 = 0; k0 < K; k0 += 8) {
        float4 va = *(const float4*)(arow + k0 + lkq * 4);
        float4 vb = *(const float4*)(brow + k0 + lkq * 4);
        As[lkq * 4 + 0][lrow] = va.x; As[lkq * 4 + 1][lrow] = va.y;
        As[lkq * 4 + 2][lrow] = va.z; As[lkq * 4 + 3][lrow] = va.w;
        Bs[lkq * 4 + 0][lrow] = vb.x; Bs[lkq * 4 + 1][lrow] = vb.y;
        Bs[lkq * 4 + 2][lrow] = vb.z; Bs[lkq * 4 + 3][lrow] = vb.w;
        __syncthreads();
        #pragma unroll
        for (int kk = 0; kk < 8; kk++) {
            float a[8], b[8];
            *(float4*)&a[0] = *(float4*)&As[kk][ty * 8];
            *(float4*)&a[4] = *(float4*)&As[kk][ty * 8 + 4];
            *(float4*)&b[0] = *(float4*)&Bs[kk][tx * 8];
            *(float4*)&b[4] = *(float4*)&Bs[kk][tx * 8 + 4];
            #pragma unroll
            for (int i = 0; i < 8; i++)
                #pragma unroll
                for (int j = 0; j < 8; j++) acc[i][j] += a[i] * b[j];
        }
        __syncthreads();
    }

    float bv[8];
    if (bias) {
        *(float4*)&bv[0] = *(const float4*)(bias + n0 + tx * 8);
        *(float4*)&bv[4] = *(const float4*)(bias + n0 + tx * 8 + 4);
    } else {
        #pragma unroll
        for (int j = 0; j < 8; j++) bv[j] = 0.f;
    }

    #pragma unroll
    for (int i = 0; i < 8; i++) {
        int m = m0 + ty * 8 + i;
        float* crow = C + (size_t)m * N + n0 + tx * 8;
        float o[8];
        #pragma unroll
        for (int j = 0; j < 8; j++) {
            float v = acc[i][j] + bv[j];
            if (round_tf32) v = tf32r(v);
            o[j] = v;
        }
        *(float4*)&crow[0] = *(float4*)&o[0];
        *(float4*)&crow[4] = *(float4*)&o[4];
    }
}

// ---------------- K3: LSTM scan (recurrence only through cell state) ----------------
__global__ void lstm_scan(const float* __restrict__ xg,
                          const float* __restrict__ base,
                          float* __restrict__ hs) {
    int idx = blockIdx.x * blockDim.x + threadIdx.x;  // 0..B*H-1
    int b = idx >> 9, h = idx & 511;
    float bi = base[b * G4_ + h];
    float bf = base[b * G4_ + H_ + h];
    float bg = base[b * G4_ + 2 * H_ + h];
    float bo = base[b * G4_ + 3 * H_ + h];
    float c = 0.f;
    for (int t = 0; t < T_; t++) {
        const float* xr = xg + (size_t)(t * B_ + b) * G4_;
        float i = sigf(xr[h] + bi);
        float f = sigf(xr[H_ + h] + bf);
        float g = tanhf(xr[2 * H_ + h] + bg);
        float o = sigf(xr[3 * H_ + h] + bo);
        c = f * c + i * g;
        hs[(size_t)(t * B_ + b) * H_ + h] = o * tanhf(c);
    }
}

// ---------------- K5: logits = hid @ W2^T + b2  (tf32 tensor-core GEMM) ----------------
// M=2048, N=V, K=1024. BM=BN=128, BK=32, 8 warps (2x4), warp tile 64x32, mma m16n8k8.
__global__ __launch_bounds__(256, 1)
void logits_kernel(const float* __restrict__ hid,
                   const float* __restrict__ W2,
                   const float* __restrict__ b2,
                   float* __restrict__ out) {
    const int K = H2_;
    __shared__ float As[128][36];
    __shared__ float Bs[128][36];
    __shared__ float b2s[128];

    int tid = threadIdx.x;
    int m0 = blockIdx.y * 128;
    int n0 = blockIdx.x * 128;
    int warp = tid >> 5, lane = tid & 31;
    int wm = warp >> 2;     // 0..1
    int wn = warp & 3;      // 0..3
    int g = lane >> 2, q = lane & 3;

    if (tid < 128) {
        int v = n0 + tid;
        b2s[tid] = (v < V_) ? b2[v] : 0.f;
    }

    float acc[4][4][4];
    #pragma unroll
    for (int mi = 0; mi < 4; mi++)
        #pragma unroll
        for (int ni = 0; ni < 4; ni++)
            #pragma unroll
            for (int r = 0; r < 4; r++) acc[mi][ni][r] = 0.f;

    // per-thread global load coords: 4 float4 each for A and B per k-tile
    int lr[4], lk[4];
    #pragma unroll
    for (int i = 0; i < 4; i++) {
        int f = tid + i * 256;
        lr[i] = f >> 3;        // 0..127
        lk[i] = (f & 7) * 4;   // 0,4,...,28
    }

    float4 pa[4], pb[4];
    // prefetch first k-tile
    #pragma unroll
    for (int i = 0; i < 4; i++) {
        pa[i] = *(const float4*)(hid + (size_t)(m0 + lr[i]) * K + lk[i]);
        int n = n0 + lr[i];
        if (n < V_) pb[i] = *(const float4*)(W2 + (size_t)n * K + lk[i]);
        else        pb[i] = make_float4(0.f, 0.f, 0.f, 0.f);
    }

    for (int k0 = 0; k0 < K; k0 += 32) {
        // stage to smem (round B to tf32 here; hid was rounded at K4 epilogue)
        #pragma unroll
        for (int i = 0; i < 4; i++) {
            *(float4*)&As[lr[i]][lk[i]] = pa[i];
            float4 v = pb[i];
            v.x = tf32r(v.x); v.y = tf32r(v.y); v.z = tf32r(v.z); v.w = tf32r(v.w);
            *(float4*)&Bs[lr[i]][lk[i]] = v;
        }
        __syncthreads();

        // prefetch next tile while computing this one
        int kn = k0 + 32;
        if (kn < K) {
            #pragma unroll
            for (int i = 0; i < 4; i++) {
                pa[i] = *(const float4*)(hid + (size_t)(m0 + lr[i]) * K + kn + lk[i]);
                int n = n0 + lr[i];
                if (n < V_) pb[i] = *(const float4*)(W2 + (size_t)n * K + kn + lk[i]);
                else        pb[i] = make_float4(0.f, 0.f, 0.f, 0.f);
            }
        }

        #pragma unroll
        for (int kk = 0; kk < 32; kk += 8) {
            float a[4][4], b[4][2];
            #pragma unroll
            for (int mi = 0; mi < 4; mi++) {
                int r = wm * 64 + mi * 16;
                a[mi][0] = As[r + g][kk + q];
                a[mi][1] = As[r + g + 8][kk + q];
                a[mi][2] = As[r + g][kk + q + 4];
                a[mi][3] = As[r + g + 8][kk + q + 4];
            }
            #pragma unroll
            for (int ni = 0; ni < 4; ni++) {
                int c = wn * 32 + ni * 8 + g;
                b[ni][0] = Bs[c][kk + q];
                b[ni][1] = Bs[c][kk + q + 4];
            }
            #pragma unroll
            for (int mi = 0; mi < 4; mi++)
                #pragma unroll
                for (int ni = 0; ni < 4; ni++)
                    mma_tf32(acc[mi][ni], a[mi], b[ni]);
        }
        __syncthreads();
    }

    // epilogue: out[b][t][v] with m = t*B + b
    #pragma unroll
    for (int mi = 0; mi < 4; mi++) {
        int mA = m0 + wm * 64 + mi * 16 + g;
        int mB = mA + 8;
        size_t offA = ((size_t)(mA & 31) * T_ + (mA >> 5)) * (size_t)V_;
        size_t offB = ((size_t)(mB & 31) * T_ + (mB >> 5)) * (size_t)V_;
        #pragma unroll
        for (int ni = 0; ni < 4; ni++) {
            int c = wn * 32 + ni * 8 + q * 2;
            int v = n0 + c;
            if (v < V_) {
                out[offA + v] = acc[mi][ni][0] + b2s[c];
                out[offB + v] = acc[mi][ni][2] + b2s[c];
                if (v + 1 < V_) {
                    out[offA + v + 1] = acc[mi][ni][1] + b2s[c + 1];
                    out[offB + v + 1] = acc[mi][ni][3] + b2s[c + 1];
                }
            }
        }
    }
}

// ---------------- launch ----------------
extern "C" void kernel_launch(void* const* d_in, const int* in_sizes, int n_in,
                              void* d_out, int out_size) {
    const float* features = (const float*)d_in[0];
    const int*   captions = (const int*)d_in[1];
    const float* emb      = (const float*)d_in[2];
    const float* W_ih     = (const float*)d_in[3];
    const float* W_hh     = (const float*)d_in[4];
    const float* b_ih     = (const float*)d_in[5];
    const float* b_hh     = (const float*)d_in[6];
    const float* W1       = (const float*)d_in[7];
    const float* b1       = (const float*)d_in[8];
    const float* W2       = (const float*)d_in[9];
    const float* b2       = (const float*)d_in[10];
    float* out = (float*)d_out;

    void *p_base, *p_xg, *p_hs, *p_hid;
    cudaGetSymbolAddress(&p_base, g_base);
    cudaGetSymbolAddress(&p_xg,   g_xg);
    cudaGetSymbolAddress(&p_hs,   g_hs);
    cudaGetSymbolAddress(&p_hid,  g_hid);
    float* base = (float*)p_base;
    float* xg   = (float*)p_xg;
    float* hs   = (float*)p_hs;
    float* hid  = (float*)p_hid;

    // K1: base gates
    base_kernel<<<B_, 256>>>(features, W_hh, b_ih, b_hh, base);

    // K2: x_gates = gather(emb, captions-shifted) @ W_ih^T   (no bias; folded into base)
    {
        dim3 grid(G4_ / 128, M_ / 128);
        sgemm_tn<<<grid, 256>>>(nullptr, W_ih, nullptr, xg,
                                M_, G4_, E_, captions, emb, 0);
    }

    // K3: LSTM scan
    lstm_scan<<<(B_ * H_) / 256, 256>>>(xg, base, hs);

    // K4: hid = hs @ W1^T + b1   (round to tf32 at store)
    {
        dim3 grid(H2_ / 128, M_ / 128);
        sgemm_tn<<<grid, 256>>>(hs, W1, b1, hid,
                                M_, H2_, H_, nullptr, nullptr, 1);
    }

    // K5: logits = hid @ W2^T + b2 -> out[b][t][v]
    {
        dim3 grid((V_ + 127) / 128, M_ / 128);
        logits_kernel<<<grid, 256>>>(hid, W2, b2, out);
    }
}

// round 6
// speedup vs baseline: 1.2044x; 1.2044x over previous
#include <cuda_runtime.h>
#include <cuda_bf16.h>
#include <cstdint>

// Problem constants
#define B_  32
#define T_  64
#define V_  50257
#define E_  256
#define H_  512
#define G4_ 2048   // 4*H
#define H2_ 1024   // 2*H
#define M_  2048   // T*B
#define VPAD2_ 50432  // 197*256

// K5 tiling
#define BM_ 128
#define BN_ 256
#define BK_ 32
#define NKT_ (H2_ / BK_)          // 32
#define ST_A_FLOATS 4096          // 128*32
#define ST_B_FLOATS 8192          // 256*32
#define ST_FLOATS   12288         // per stage (48KB)
#define SMEM_DYN    (2 * ST_FLOATS * 4)   // 98304

// ---------------- scratch (device globals; no allocation allowed) ----------------
__device__ float g_base[B_ * G4_];
__device__ float g_xg[M_ * G4_];
__device__ float g_hs[M_ * H_];
__device__ float g_hid[M_ * H2_];
__device__ __align__(16) float g_hidp[(size_t)M_ * H2_];          // permuted, tf32-rounded
__device__ __align__(16) float g_w2p[(size_t)VPAD2_ * H2_];        // permuted, tf32-rounded, zero-padded

// ---------------- helpers ----------------
__device__ __forceinline__ float tf32r(float x) {
    uint32_t u;
    asm("cvt.rna.tf32.f32 %0, %1;" : "=r"(u) : "f"(x));
    return __uint_as_float(u);
}

__device__ __forceinline__ void mma_tf32(float* d, const float* a, const float* b) {
    asm volatile(
        "mma.sync.aligned.m16n8k8.row.col.f32.tf32.tf32.f32 "
        "{%0,%1,%2,%3}, {%4,%5,%6,%7}, {%8,%9}, {%0,%1,%2,%3};\n"
        : "+f"(d[0]), "+f"(d[1]), "+f"(d[2]), "+f"(d[3])
        : "r"(__float_as_uint(a[0])), "r"(__float_as_uint(a[1])),
          "r"(__float_as_uint(a[2])), "r"(__float_as_uint(a[3])),
          "r"(__float_as_uint(b[0])), "r"(__float_as_uint(b[1])));
}

__device__ __forceinline__ float sigf(float x) {
    return 1.f / (1.f + __expf(-x));
}

__device__ __forceinline__ uint32_t smem_u32(const void* p) {
    return (uint32_t)__cvta_generic_to_shared(p);
}

__device__ __forceinline__ void cp16(uint32_t dst, const void* src) {
    asm volatile("cp.async.cg.shared.global [%0], [%1], 16;\n"
                 :: "r"(dst), "l"(src) : "memory");
}

// ---------------- K1: base gates = features @ W_hh^T + b_ih + b_hh ----------------
__global__ void base_kernel(const float* __restrict__ feat,
                            const float* __restrict__ W_hh,
                            const float* __restrict__ b_ih,
                            const float* __restrict__ b_hh,
                            float* __restrict__ base) {
    __shared__ float4 f4[H_ / 4];
    int b = blockIdx.x;
    if (threadIdx.x < H_ / 4)
        f4[threadIdx.x] = ((const float4*)(feat + (size_t)b * H_))[threadIdx.x];
    __syncthreads();
    for (int g = threadIdx.x; g < G4_; g += blockDim.x) {
        const float4* w4 = (const float4*)(W_hh + (size_t)g * H_);
        float s = 0.f;
        #pragma unroll 8
        for (int k = 0; k < H_ / 4; k++) {
            float4 w = w4[k], f = f4[k];
            s += w.x * f.x + w.y * f.y + w.z * f.z + w.w * f.w;
        }
        base[b * G4_ + g] = s + b_ih[g] + b_hh[g];
    }
}

// ---------------- generic 128x128x8 SGEMM ----------------
__global__ __launch_bounds__(256)
void sgemm_tn(const float* __restrict__ A, const float* __restrict__ Bm,
              const float* __restrict__ bias, float* __restrict__ C,
              int M, int N, int K,
              const int* __restrict__ captions, const float* __restrict__ embA) {
    __shared__ float As[8][132];
    __shared__ float Bs[8][132];
    int tid = threadIdx.x;
    int tx = tid & 15, ty = tid >> 4;
    int m0 = blockIdx.y * 128, n0 = blockIdx.x * 128;

    float acc[8][8];
    #pragma unroll
    for (int i = 0; i < 8; i++)
        #pragma unroll
        for (int j = 0; j < 8; j++) acc[i][j] = 0.f;

    int lrow = tid >> 1;
    int lkq  = tid & 1;
    const float* arow;
    if (captions) {
        int m = m0 + lrow;
        int bb = m & 31, tt = m >> 5;
        int ct = (tt == 0) ? 0 : (tt - 1);
        int tok = captions[bb * T_ + ct];
        arow = embA + (size_t)tok * K;
    } else {
        arow = A + (size_t)(m0 + lrow) * K;
    }
    const float* brow = Bm + (size_t)(n0 + lrow) * K;

    for (int k0 = 0; k0 < K; k0 += 8) {
        float4 va = *(const float4*)(arow + k0 + lkq * 4);
        float4 vb = *(const float4*)(brow + k0 + lkq * 4);
        As[lkq * 4 + 0][lrow] = va.x; As[lkq * 4 + 1][lrow] = va.y;
        As[lkq * 4 + 2][lrow] = va.z; As[lkq * 4 + 3][lrow] = va.w;
        Bs[lkq * 4 + 0][lrow] = vb.x; Bs[lkq * 4 + 1][lrow] = vb.y;
        Bs[lkq * 4 + 2][lrow] = vb.z; Bs[lkq * 4 + 3][lrow] = vb.w;
        __syncthreads();
        #pragma unroll
        for (int kk = 0; kk < 8; kk++) {
            float a[8], b[8];
            *(float4*)&a[0] = *(float4*)&As[kk][ty * 8];
            *(float4*)&a[4] = *(float4*)&As[kk][ty * 8 + 4];
            *(float4*)&b[0] = *(float4*)&Bs[kk][tx * 8];
            *(float4*)&b[4] = *(float4*)&Bs[kk][tx * 8 + 4];
            #pragma unroll
            for (int i = 0; i < 8; i++)
                #pragma unroll
                for (int j = 0; j < 8; j++) acc[i][j] += a[i] * b[j];
        }
        __syncthreads();
    }

    float bv[8];
    if (bias) {
        *(float4*)&bv[0] = *(const float4*)(bias + n0 + tx * 8);
        *(float4*)&bv[4] = *(const float4*)(bias + n0 + tx * 8 + 4);
    } else {
        #pragma unroll
        for (int j = 0; j < 8; j++) bv[j] = 0.f;
    }

    #pragma unroll
    for (int i = 0; i < 8; i++) {
        int m = m0 + ty * 8 + i;
        float* crow = C + (size_t)m * N + n0 + tx * 8;
        float o[8];
        #pragma unroll
        for (int j = 0; j < 8; j++) o[j] = acc[i][j] + bv[j];
        *(float4*)&crow[0] = *(float4*)&o[0];
        *(float4*)&crow[4] = *(float4*)&o[4];
    }
}

// ---------------- K3: LSTM scan ----------------
__global__ void lstm_scan(const float* __restrict__ xg,
                          const float* __restrict__ base,
                          float* __restrict__ hs) {
    int idx = blockIdx.x * blockDim.x + threadIdx.x;
    int b = idx >> 9, h = idx & 511;
    float bi = base[b * G4_ + h];
    float bf = base[b * G4_ + H_ + h];
    float bg = base[b * G4_ + 2 * H_ + h];
    float bo = base[b * G4_ + 3 * H_ + h];
    float c = 0.f;
    for (int t = 0; t < T_; t++) {
        const float* xr = xg + (size_t)(t * B_ + b) * G4_;
        float i = sigf(xr[h] + bi);
        float f = sigf(xr[H_ + h] + bf);
        float g = tanhf(xr[2 * H_ + h] + bg);
        float o = sigf(xr[3 * H_ + h] + bo);
        c = f * c + i * g;
        hs[(size_t)(t * B_ + b) * H_ + h] = o * tanhf(c);
    }
}

// ---------------- prep: permute W2 into mma-fragment order (tf32-rounded) ----------------
// Layout: [nb=n>>8][kt=k>>5][tn2=((n&255)>>3)>>1][kk=(k>>3)&3] block of 128 floats:
//   idx_in_block = lane*4 + reg,  lane = (n&7)*4 + (k&3),  reg = ((n>>3)&1)*2 + ((k>>2)&1)
__global__ void permB_kernel(const float* __restrict__ W2, float* __restrict__ outp) {
    size_t stride = (size_t)gridDim.x * blockDim.x;
    size_t total = (size_t)VPAD2_ * 256;   // float4 count per row = 256
    for (size_t i = (size_t)blockIdx.x * blockDim.x + threadIdx.x; i < total; i += stride) {
        int j = (int)(i & 255);
        int n = (int)(i >> 8);
        float4 v;
        if (n < V_) v = ((const float4*)W2)[(size_t)n * 256 + j];
        else        v = make_float4(0.f, 0.f, 0.f, 0.f);
        int nb = n >> 8, nr = n & 255, tn = nr >> 3, g = nr & 7;
        int tn2 = tn >> 1, pos = tn & 1;
        int kt = j >> 3, kk = (j >> 1) & 3, h = j & 1;
        size_t bb = ((((size_t)(nb * 32 + kt) * 16 + tn2) * 4 + kk) * 128);
        int reg = pos * 2 + h;
        float* d = outp + bb + g * 16 + reg;
        d[0]  = tf32r(v.x);
        d[4]  = tf32r(v.y);
        d[8]  = tf32r(v.z);
        d[12] = tf32r(v.w);
    }
}

// ---------------- prep: permute hid into mma-fragment order (tf32-rounded) ----------------
// Layout: [mb=m>>7][kt][tm=((m&127)>>4)][kk] block of 128 floats:
//   lane = (m&7... g = (m&15)&7)*4 + (k&3), reg = ((m>>3)&1) + 2*((k>>2)&1)
__global__ void permA_kernel(const float* __restrict__ hid, float* __restrict__ outp) {
    size_t stride = (size_t)gridDim.x * blockDim.x;
    size_t total = (size_t)M_ * 256;
    for (size_t i = (size_t)blockIdx.x * blockDim.x + threadIdx.x; i < total; i += stride) {
        int j = (int)(i & 255);
        int m = (int)(i >> 8);
        float4 v = ((const float4*)hid)[(size_t)m * 256 + j];
        int mb = m >> 7, mr = m & 127, tm = mr >> 4, r = mr & 15;
        int g = r & 7, hi = r >> 3;
        int kt = j >> 3, kk = (j >> 1) & 3, h = j & 1;
        size_t bb = ((((size_t)(mb * 32 + kt) * 8 + tm) * 4 + kk) * 128);
        int reg = hi + 2 * h;
        float* d = outp + bb + g * 16 + reg;
        d[0]  = tf32r(v.x);
        d[4]  = tf32r(v.y);
        d[8]  = tf32r(v.z);
        d[12] = tf32r(v.w);
    }
}

// ---------------- K5: logits = hid @ W2^T + b2 (tf32 mma, fragment-permuted operands) ----------------
// CTA 128x256, warps 2x4, warp tile 64x64. cp.async double buffer.
__global__ __launch_bounds__(256, 1)
void logits_mma(const float* __restrict__ Ap, const float* __restrict__ Bp,
                const float* __restrict__ b2, float* __restrict__ out) {
    __shared__ float b2s[BN_];
    extern __shared__ float st[];   // 2 stages x 12288 floats

    int tid = threadIdx.x, lane = tid & 31, warp = tid >> 5;
    int wm = warp >> 2, wn = warp & 3;
    int mb = blockIdx.x, nb = blockIdx.y;

    { int v = nb * BN_ + tid; b2s[tid] = (v < V_) ? b2[v] : 0.f; }

    const float4* Asrc = (const float4*)(Ap + (size_t)mb * NKT_ * ST_A_FLOATS);
    const float4* Bsrc = (const float4*)(Bp + (size_t)nb * NKT_ * ST_B_FLOATS);
    uint32_t stb = smem_u32(st);

    // prefetch k-tile kt into stage (kt&1)
    auto prefetch = [&](int kt) {
        uint32_t d = stb + (kt & 1) * (ST_FLOATS * 4);
        const float4* a4 = Asrc + (size_t)kt * (ST_A_FLOATS / 4);
        const float4* b4 = Bsrc + (size_t)kt * (ST_B_FLOATS / 4);
        #pragma unroll
        for (int i = 0; i < 4; i++)
            cp16(d + (tid + i * 256) * 16, a4 + tid + i * 256);
        uint32_t db = d + ST_A_FLOATS * 4;
        #pragma unroll
        for (int i = 0; i < 8; i++)
            cp16(db + (tid + i * 256) * 16, b4 + tid + i * 256);
        asm volatile("cp.async.commit_group;\n" ::: "memory");
    };

    float acc[4][8][4];
    #pragma unroll
    for (int mi = 0; mi < 4; mi++)
        #pragma unroll
        for (int ni = 0; ni < 8; ni++)
            #pragma unroll
            for (int r = 0; r < 4; r++) acc[mi][ni][r] = 0.f;

    prefetch(0);
    prefetch(1);

    for (int kt = 0; kt < NKT_; kt++) {
        if (kt < NKT_ - 2)
            asm volatile("cp.async.wait_group 1;\n" ::: "memory");
        else
            asm volatile("cp.async.wait_group 0;\n" ::: "memory");
        __syncthreads();

        const float* S  = st + (kt & 1) * ST_FLOATS;
        const float* SA = S;
        const float* SB = S + ST_A_FLOATS;

        #pragma unroll
        for (int kk = 0; kk < 4; kk++) {
            float4 af[4], bf[4];
            #pragma unroll
            for (int mi = 0; mi < 4; mi++)
                af[mi] = *(const float4*)(SA + (((wm * 4 + mi) * 4 + kk) * 32 + lane) * 4);
            #pragma unroll
            for (int n2 = 0; n2 < 4; n2++)
                bf[n2] = *(const float4*)(SB + (((wn * 4 + n2) * 4 + kk) * 32 + lane) * 4);
            #pragma unroll
            for (int mi = 0; mi < 4; mi++)
                #pragma unroll
                for (int n2 = 0; n2 < 4; n2++) {
                    mma_tf32(acc[mi][n2 * 2],     &af[mi].x, &bf[n2].x);
                    mma_tf32(acc[mi][n2 * 2 + 1], &af[mi].x, &bf[n2].z);
                }
        }
        __syncthreads();
        if (kt + 2 < NKT_) prefetch(kt + 2);
    }

    // epilogue: m = t*B+b ; out[b][t][v]
    int g = lane >> 2, q = lane & 3;
    #pragma unroll
    for (int mi = 0; mi < 4; mi++) {
        int mA = mb * 128 + wm * 64 + mi * 16 + g;
        int mB = mA + 8;
        size_t offA = ((size_t)(mA & 31) * T_ + (size_t)(mA >> 5)) * (size_t)V_;
        size_t offB = ((size_t)(mB & 31) * T_ + (size_t)(mB >> 5)) * (size_t)V_;
        #pragma unroll
        for (int ni = 0; ni < 8; ni++) {
            int c = wn * 64 + ni * 8 + q * 2;
            int n = nb * BN_ + c;
            if (n < V_) {
                out[offA + n] = acc[mi][ni][0] + b2s[c];
                out[offB + n] = acc[mi][ni][2] + b2s[c];
                if (n + 1 < V_) {
                    out[offA + n + 1] = acc[mi][ni][1] + b2s[c + 1];
                    out[offB + n + 1] = acc[mi][ni][3] + b2s[c + 1];
                }
            }
        }
    }
}

// ---------------- launch ----------------
extern "C" void kernel_launch(void* const* d_in, const int* in_sizes, int n_in,
                              void* d_out, int out_size) {
    const float* features = (const float*)d_in[0];
    const int*   captions = (const int*)d_in[1];
    const float* emb      = (const float*)d_in[2];
    const float* W_ih     = (const float*)d_in[3];
    const float* W_hh     = (const float*)d_in[4];
    const float* b_ih     = (const float*)d_in[5];
    const float* b_hh     = (const float*)d_in[6];
    const float* W1       = (const float*)d_in[7];
    const float* b1       = (const float*)d_in[8];
    const float* W2       = (const float*)d_in[9];
    const float* b2       = (const float*)d_in[10];
    float* out = (float*)d_out;

    void *p_base, *p_xg, *p_hs, *p_hid, *p_hidp, *p_w2p;
    cudaGetSymbolAddress(&p_base, g_base);
    cudaGetSymbolAddress(&p_xg,   g_xg);
    cudaGetSymbolAddress(&p_hs,   g_hs);
    cudaGetSymbolAddress(&p_hid,  g_hid);
    cudaGetSymbolAddress(&p_hidp, g_hidp);
    cudaGetSymbolAddress(&p_w2p,  g_w2p);
    float* base = (float*)p_base;
    float* xg   = (float*)p_xg;
    float* hs   = (float*)p_hs;
    float* hid  = (float*)p_hid;
    float* hidp = (float*)p_hidp;
    float* w2p  = (float*)p_w2p;

    cudaFuncSetAttribute(logits_mma, cudaFuncAttributeMaxDynamicSharedMemorySize, SMEM_DYN);

    // K0: permute + tf32-round W2 (runs concurrently with K1..K4 chain on the stream order)
    permB_kernel<<<2048, 256>>>(W2, w2p);

    // K1: base gates
    base_kernel<<<B_, 256>>>(features, W_hh, b_ih, b_hh, base);

    // K2: x_gates = gather(emb) @ W_ih^T
    {
        dim3 grid(G4_ / 128, M_ / 128);
        sgemm_tn<<<grid, 256>>>(nullptr, W_ih, nullptr, xg,
                                M_, G4_, E_, captions, emb);
    }

    // K3: LSTM scan
    lstm_scan<<<(B_ * H_) / 256, 256>>>(xg, base, hs);

    // K4: hid = hs @ W1^T + b1 (fp32)
    {
        dim3 grid(H2_ / 128, M_ / 128);
        sgemm_tn<<<grid, 256>>>(hs, W1, b1, hid,
                                M_, H2_, H_, nullptr, nullptr);
    }

    // K4b: permute + tf32-round hid
    permA_kernel<<<512, 256>>>(hid, hidp);

    // K5: logits via tf32 mma with fragment-permuted operands
    {
        dim3 grid(M_ / BM_, VPAD2_ / BN_);   // (16, 197)
        logits_mma<<<grid, 256, SMEM_DYN>>>(hidp, w2p, b2, out);
    }
}

// round 7
// speedup vs baseline: 1.2466x; 1.0350x over previous
#include <cuda_runtime.h>
#include <cuda_bf16.h>
#include <cstdint>

// Problem constants
#define B_  32
#define T_  64
#define V_  50257
#define E_  256
#define H_  512
#define G4_ 2048   // 4*H
#define H2_ 1024   // 2*H
#define M_  2048   // T*B
#define VPAD2_ 50432  // 197*256

// K5 tiling: CTA 128x256, 512 threads (16 warps, warp tile 64x32), BK=64
#define BM_ 128
#define BN_ 256
#define BK_ 64
#define NKT_ (H2_ / BK_)          // 16
#define ST_A_FLOATS 8192          // 128*64
#define ST_B_FLOATS 16384         // 256*64
#define ST_FLOATS   24576         // per stage (96KB)
#define SMEM_DYN    (2 * ST_FLOATS * 4)   // 196608

// ---------------- scratch (device globals; no allocation allowed) ----------------
__device__ float g_base[B_ * G4_];
__device__ float g_xg[M_ * G4_];
__device__ float g_hs[M_ * H_];
__device__ float g_hid[M_ * H2_];
__device__ __align__(16) float g_hidp[(size_t)M_ * H2_];          // permuted, tf32-rounded
__device__ __align__(16) float g_w2p[(size_t)VPAD2_ * H2_];        // permuted, tf32-rounded, zero-padded

// ---------------- helpers ----------------
__device__ __forceinline__ float tf32r(float x) {
    uint32_t u;
    asm("cvt.rna.tf32.f32 %0, %1;" : "=r"(u) : "f"(x));
    return __uint_as_float(u);
}

__device__ __forceinline__ void mma_tf32(float* d, const float* a, const float* b) {
    asm volatile(
        "mma.sync.aligned.m16n8k8.row.col.f32.tf32.tf32.f32 "
        "{%0,%1,%2,%3}, {%4,%5,%6,%7}, {%8,%9}, {%0,%1,%2,%3};\n"
        : "+f"(d[0]), "+f"(d[1]), "+f"(d[2]), "+f"(d[3])
        : "r"(__float_as_uint(a[0])), "r"(__float_as_uint(a[1])),
          "r"(__float_as_uint(a[2])), "r"(__float_as_uint(a[3])),
          "r"(__float_as_uint(b[0])), "r"(__float_as_uint(b[1])));
}

__device__ __forceinline__ float sigf(float x) {
    return __fdividef(1.f, 1.f + __expf(-x));
}
__device__ __forceinline__ float ftanh(float x) {
    float e = __expf(2.f * x);
    return 1.f - __fdividef(2.f, e + 1.f);
}

__device__ __forceinline__ uint32_t smem_u32(const void* p) {
    return (uint32_t)__cvta_generic_to_shared(p);
}

__device__ __forceinline__ void cp16(uint32_t dst, const void* src) {
    asm volatile("cp.async.cg.shared.global [%0], [%1], 16;\n"
                 :: "r"(dst), "l"(src) : "memory");
}

// ---------------- K1: base gates = features @ W_hh^T + b_ih + b_hh ----------------
__global__ void base_kernel(const float* __restrict__ feat,
                            const float* __restrict__ W_hh,
                            const float* __restrict__ b_ih,
                            const float* __restrict__ b_hh,
                            float* __restrict__ base) {
    __shared__ float4 f4[H_ / 4];
    int b = blockIdx.x;
    if (threadIdx.x < H_ / 4)
        f4[threadIdx.x] = ((const float4*)(feat + (size_t)b * H_))[threadIdx.x];
    __syncthreads();
    for (int g = threadIdx.x; g < G4_; g += blockDim.x) {
        const float4* w4 = (const float4*)(W_hh + (size_t)g * H_);
        float s = 0.f;
        #pragma unroll 8
        for (int k = 0; k < H_ / 4; k++) {
            float4 w = w4[k], f = f4[k];
            s += w.x * f.x + w.y * f.y + w.z * f.z + w.w * f.w;
        }
        base[b * G4_ + g] = s + b_ih[g] + b_hh[g];
    }
}

// ---------------- generic 128x128x8 SGEMM ----------------
__global__ __launch_bounds__(256)
void sgemm_tn(const float* __restrict__ A, const float* __restrict__ Bm,
              const float* __restrict__ bias, float* __restrict__ C,
              int M, int N, int K,
              const int* __restrict__ captions, const float* __restrict__ embA) {
    __shared__ float As[8][132];
    __shared__ float Bs[8][132];
    int tid = threadIdx.x;
    int tx = tid & 15, ty = tid >> 4;
    int m0 = blockIdx.y * 128, n0 = blockIdx.x * 128;

    float acc[8][8];
    #pragma unroll
    for (int i = 0; i < 8; i++)
        #pragma unroll
        for (int j = 0; j < 8; j++) acc[i][j] = 0.f;

    int lrow = tid >> 1;
    int lkq  = tid & 1;
    const float* arow;
    if (captions) {
        int m = m0 + lrow;
        int bb = m & 31, tt = m >> 5;
        int ct = (tt == 0) ? 0 : (tt - 1);
        int tok = captions[bb * T_ + ct];
        arow = embA + (size_t)tok * K;
    } else {
        arow = A + (size_t)(m0 + lrow) * K;
    }
    const float* brow = Bm + (size_t)(n0 + lrow) * K;

    for (int k0 = 0; k0 < K; k0 += 8) {
        float4 va = *(const float4*)(arow + k0 + lkq * 4);
        float4 vb = *(const float4*)(brow + k0 + lkq * 4);
        As[lkq * 4 + 0][lrow] = va.x; As[lkq * 4 + 1][lrow] = va.y;
        As[lkq * 4 + 2][lrow] = va.z; As[lkq * 4 + 3][lrow] = va.w;
        Bs[lkq * 4 + 0][lrow] = vb.x; Bs[lkq * 4 + 1][lrow] = vb.y;
        Bs[lkq * 4 + 2][lrow] = vb.z; Bs[lkq * 4 + 3][lrow] = vb.w;
        __syncthreads();
        #pragma unroll
        for (int kk = 0; kk < 8; kk++) {
            float a[8], b[8];
            *(float4*)&a[0] = *(float4*)&As[kk][ty * 8];
            *(float4*)&a[4] = *(float4*)&As[kk][ty * 8 + 4];
            *(float4*)&b[0] = *(float4*)&Bs[kk][tx * 8];
            *(float4*)&b[4] = *(float4*)&Bs[kk][tx * 8 + 4];
            #pragma unroll
            for (int i = 0; i < 8; i++)
                #pragma unroll
                for (int j = 0; j < 8; j++) acc[i][j] += a[i] * b[j];
        }
        __syncthreads();
    }

    float bv[8];
    if (bias) {
        *(float4*)&bv[0] = *(const float4*)(bias + n0 + tx * 8);
        *(float4*)&bv[4] = *(const float4*)(bias + n0 + tx * 8 + 4);
    } else {
        #pragma unroll
        for (int j = 0; j < 8; j++) bv[j] = 0.f;
    }

    #pragma unroll
    for (int i = 0; i < 8; i++) {
        int m = m0 + ty * 8 + i;
        float* crow = C + (size_t)m * N + n0 + tx * 8;
        float o[8];
        #pragma unroll
        for (int j = 0; j < 8; j++) o[j] = acc[i][j] + bv[j];
        *(float4*)&crow[0] = *(float4*)&o[0];
        *(float4*)&crow[4] = *(float4*)&o[4];
    }
}

// ---------------- K3: LSTM scan (depth-8 prefetch, fast transcendentals) ----------------
__global__ void lstm_scan(const float* __restrict__ xg,
                          const float* __restrict__ base,
                          float* __restrict__ hs) {
    int idx = blockIdx.x * blockDim.x + threadIdx.x;   // 0..B*H-1
    int b = idx >> 9, h = idx & 511;
    float bi = base[b * G4_ + h];
    float bff = base[b * G4_ + H_ + h];
    float bg = base[b * G4_ + 2 * H_ + h];
    float bo = base[b * G4_ + 3 * H_ + h];

    const float* xr = xg + (size_t)b * G4_ + h;
    const size_t step = (size_t)B_ * G4_;

    float4 pf[8];
    #pragma unroll
    for (int j = 0; j < 8; j++) {
        const float* p = xr + (size_t)j * step;
        pf[j] = make_float4(p[0], p[H_], p[2 * H_], p[3 * H_]);
    }

    float c = 0.f;
    float* hp = hs + (size_t)b * H_ + h;
    #pragma unroll 8
    for (int t = 0; t < T_; t++) {
        float4 cur = pf[t & 7];
        if (t + 8 < T_) {
            const float* p = xr + (size_t)(t + 8) * step;
            pf[t & 7] = make_float4(p[0], p[H_], p[2 * H_], p[3 * H_]);
        }
        float i = sigf(cur.x + bi);
        float f = sigf(cur.y + bff);
        float g = ftanh(cur.z + bg);
        float o = sigf(cur.w + bo);
        c = f * c + i * g;
        hp[(size_t)t * B_ * H_] = o * ftanh(c);
    }
}

// ---------------- prep: permute W2 into mma-fragment order (tf32-rounded) ----------------
__global__ void permB_kernel(const float* __restrict__ W2, float* __restrict__ outp) {
    size_t stride = (size_t)gridDim.x * blockDim.x;
    size_t total = (size_t)VPAD2_ * 256;
    for (size_t i = (size_t)blockIdx.x * blockDim.x + threadIdx.x; i < total; i += stride) {
        int j = (int)(i & 255);
        int n = (int)(i >> 8);
        float4 v;
        if (n < V_) v = ((const float4*)W2)[(size_t)n * 256 + j];
        else        v = make_float4(0.f, 0.f, 0.f, 0.f);
        int nb = n >> 8, nr = n & 255, tn = nr >> 3, g = nr & 7;
        int tn2 = tn >> 1, pos = tn & 1;
        int kt = j >> 3, kk = (j >> 1) & 3, h = j & 1;
        size_t bb = ((((size_t)(nb * 32 + kt) * 16 + tn2) * 4 + kk) * 128);
        int reg = pos * 2 + h;
        float* d = outp + bb + g * 16 + reg;
        d[0]  = tf32r(v.x);
        d[4]  = tf32r(v.y);
        d[8]  = tf32r(v.z);
        d[12] = tf32r(v.w);
    }
}

// ---------------- prep: permute hid into mma-fragment order (tf32-rounded) ----------------
__global__ void permA_kernel(const float* __restrict__ hid, float* __restrict__ outp) {
    size_t stride = (size_t)gridDim.x * blockDim.x;
    size_t total = (size_t)M_ * 256;
    for (size_t i = (size_t)blockIdx.x * blockDim.x + threadIdx.x; i < total; i += stride) {
        int j = (int)(i & 255);
        int m = (int)(i >> 8);
        float4 v = ((const float4*)hid)[(size_t)m * 256 + j];
        int mb = m >> 7, mr = m & 127, tm = mr >> 4, r = mr & 15;
        int g = r & 7, hi = r >> 3;
        int kt = j >> 3, kk = (j >> 1) & 3, h = j & 1;
        size_t bb = ((((size_t)(mb * 32 + kt) * 8 + tm) * 4 + kk) * 128);
        int reg = hi + 2 * h;
        float* d = outp + bb + g * 16 + reg;
        d[0]  = tf32r(v.x);
        d[4]  = tf32r(v.y);
        d[8]  = tf32r(v.z);
        d[12] = tf32r(v.w);
    }
}

// ---------------- K5: logits = hid @ W2^T + b2 (tf32 mma, fragment-permuted operands) ----------------
// CTA 128x256, 16 warps (2x8), warp tile 64x32, BK=64, cp.async double buffer.
__global__ __launch_bounds__(512, 1)
void logits_mma(const float* __restrict__ Ap, const float* __restrict__ Bp,
                const float* __restrict__ b2, float* __restrict__ out) {
    __shared__ float b2s[BN_];
    extern __shared__ float st[];   // 2 stages x 24576 floats

    int tid = threadIdx.x, lane = tid & 31, warp = tid >> 5;
    int wm = warp >> 3;   // 0..1  (M)
    int wn = warp & 7;    // 0..7  (N)
    int mb = blockIdx.x, nb = blockIdx.y;

    if (tid < BN_) { int v = nb * BN_ + tid; b2s[tid] = (v < V_) ? b2[v] : 0.f; }

    // permuted layouts are kt32-block granular; one BK=64 stage = 2 consecutive kt32 blocks
    const float4* Asrc = (const float4*)(Ap + (size_t)mb * 32 * 4096);
    const float4* Bsrc = (const float4*)(Bp + (size_t)nb * 32 * 8192);
    uint32_t stb = smem_u32(st);

    auto prefetch = [&](int c) {
        uint32_t d = stb + (c & 1) * (ST_FLOATS * 4);
        const float4* a4 = Asrc + (size_t)c * 2048;   // 2*4096 floats
        const float4* b4 = Bsrc + (size_t)c * 4096;   // 2*8192 floats
        #pragma unroll
        for (int i = 0; i < 4; i++)
            cp16(d + (tid + i * 512) * 16, a4 + tid + i * 512);
        uint32_t db = d + ST_A_FLOATS * 4;
        #pragma unroll
        for (int i = 0; i < 8; i++)
            cp16(db + (tid + i * 512) * 16, b4 + tid + i * 512);
        asm volatile("cp.async.commit_group;\n" ::: "memory");
    };

    float acc[4][4][4];
    #pragma unroll
    for (int mi = 0; mi < 4; mi++)
        #pragma unroll
        for (int ni = 0; ni < 4; ni++)
            #pragma unroll
            for (int r = 0; r < 4; r++) acc[mi][ni][r] = 0.f;

    prefetch(0);
    prefetch(1);

    for (int c = 0; c < NKT_; c++) {
        if (c < NKT_ - 2)
            asm volatile("cp.async.wait_group 1;\n" ::: "memory");
        else
            asm volatile("cp.async.wait_group 0;\n" ::: "memory");
        __syncthreads();

        const float* S  = st + (c & 1) * ST_FLOATS;
        const float* SA = S;                 // [h(2)][tm(8)][kk(4)][128]
        const float* SB = S + ST_A_FLOATS;   // [h(2)][tn2(16)][kk(4)][128]

        #pragma unroll
        for (int h = 0; h < 2; h++) {
            #pragma unroll
            for (int kk = 0; kk < 4; kk++) {
                float4 af[4], bf[2];
                #pragma unroll
                for (int mi = 0; mi < 4; mi++)
                    af[mi] = *(const float4*)(SA + h * 4096 +
                                              ((wm * 4 + mi) * 4 + kk) * 128 + lane * 4);
                #pragma unroll
                for (int n2 = 0; n2 < 2; n2++)
                    bf[n2] = *(const float4*)(SB + h * 8192 +
                                              ((wn * 2 + n2) * 4 + kk) * 128 + lane * 4);
                #pragma unroll
                for (int mi = 0; mi < 4; mi++)
                    #pragma unroll
                    for (int n2 = 0; n2 < 2; n2++) {
                        mma_tf32(acc[mi][n2 * 2],     &af[mi].x, &bf[n2].x);
                        mma_tf32(acc[mi][n2 * 2 + 1], &af[mi].x, &bf[n2].z);
                    }
            }
        }
        __syncthreads();
        if (c + 2 < NKT_) prefetch(c + 2);
    }

    // epilogue: m = t*B+b ; out[b][t][v]
    int g = lane >> 2, q = lane & 3;
    #pragma unroll
    for (int mi = 0; mi < 4; mi++) {
        int mA = mb * 128 + wm * 64 + mi * 16 + g;
        int mB = mA + 8;
        size_t offA = ((size_t)(mA & 31) * T_ + (size_t)(mA >> 5)) * (size_t)V_;
        size_t offB = ((size_t)(mB & 31) * T_ + (size_t)(mB >> 5)) * (size_t)V_;
        #pragma unroll
        for (int ni = 0; ni < 4; ni++) {
            int cc = wn * 32 + (ni >> 1) * 16 + (ni & 1) * 8 + q * 2;
            int n = nb * BN_ + cc;
            if (n < V_) {
                out[offA + n] = acc[mi][ni][0] + b2s[cc];
                out[offB + n] = acc[mi][ni][2] + b2s[cc];
                if (n + 1 < V_) {
                    out[offA + n + 1] = acc[mi][ni][1] + b2s[cc + 1];
                    out[offB + n + 1] = acc[mi][ni][3] + b2s[cc + 1];
                }
            }
        }
    }
}

// ---------------- launch ----------------
extern "C" void kernel_launch(void* const* d_in, const int* in_sizes, int n_in,
                              void* d_out, int out_size) {
    const float* features = (const float*)d_in[0];
    const int*   captions = (const int*)d_in[1];
    const float* emb      = (const float*)d_in[2];
    const float* W_ih     = (const float*)d_in[3];
    const float* W_hh     = (const float*)d_in[4];
    const float* b_ih     = (const float*)d_in[5];
    const float* b_hh     = (const float*)d_in[6];
    const float* W1       = (const float*)d_in[7];
    const float* b1       = (const float*)d_in[8];
    const float* W2       = (const float*)d_in[9];
    const float* b2       = (const float*)d_in[10];
    float* out = (float*)d_out;

    void *p_base, *p_xg, *p_hs, *p_hid, *p_hidp, *p_w2p;
    cudaGetSymbolAddress(&p_base, g_base);
    cudaGetSymbolAddress(&p_xg,   g_xg);
    cudaGetSymbolAddress(&p_hs,   g_hs);
    cudaGetSymbolAddress(&p_hid,  g_hid);
    cudaGetSymbolAddress(&p_hidp, g_hidp);
    cudaGetSymbolAddress(&p_w2p,  g_w2p);
    float* base = (float*)p_base;
    float* xg   = (float*)p_xg;
    float* hs   = (float*)p_hs;
    float* hid  = (float*)p_hid;
    float* hidp = (float*)p_hidp;
    float* w2p  = (float*)p_w2p;

    cudaFuncSetAttribute(logits_mma, cudaFuncAttributeMaxDynamicSharedMemorySize, SMEM_DYN);

    // K0: permute + tf32-round W2
    permB_kernel<<<2048, 256>>>(W2, w2p);

    // K1: base gates
    base_kernel<<<B_, 256>>>(features, W_hh, b_ih, b_hh, base);

    // K2: x_gates = gather(emb) @ W_ih^T
    {
        dim3 grid(G4_ / 128, M_ / 128);
        sgemm_tn<<<grid, 256>>>(nullptr, W_ih, nullptr, xg,
                                M_, G4_, E_, captions, emb);
    }

    // K3: LSTM scan
    lstm_scan<<<128, 128>>>(xg, base, hs);

    // K4: hid = hs @ W1^T + b1 (fp32)
    {
        dim3 grid(H2_ / 128, M_ / 128);
        sgemm_tn<<<grid, 256>>>(hs, W1, b1, hid,
                                M_, H2_, H_, nullptr, nullptr);
    }

    // K4b: permute + tf32-round hid
    permA_kernel<<<512, 256>>>(hid, hidp);

    // K5: logits via tf32 mma with fragment-permuted operands
    {
        dim3 grid(M_ / BM_, VPAD2_ / BN_);   // (16, 197)
        logits_mma<<<grid, 512, SMEM_DYN>>>(hidp, w2p, b2, out);
    }
}

// round 8
// speedup vs baseline: 1.9586x; 1.5712x over previous
#include <cuda_runtime.h>
#include <cuda_fp16.h>
#include <cstdint>

// Problem constants
#define B_  32
#define T_  64
#define V_  50257
#define E_  256
#define H_  512
#define G4_ 2048   // 4*H
#define H2_ 1024   // 2*H
#define M_  2048   // T*B
#define VPAD2_ 50432  // 197*256

// K5 tiling: CTA 128x256, 512 threads (16 warps 2x8), warp tile 64x32, BK=128
#define BM_ 128
#define BN_ 256
#define BKC_ 128
#define NKT_ (H2_ / BKC_)         // 8 chunks
#define ST_A_BYTES 32768          // 128*128*2
#define ST_B_BYTES 65536          // 256*128*2
#define ST_BYTES   98304
#define SMEM_DYN   (2 * ST_BYTES) // 196608

// ---------------- scratch (device globals; no allocation allowed) ----------------
__device__ float g_base[B_ * G4_];
__device__ float g_xg[M_ * G4_];
__device__ float g_hs[M_ * H_];
__device__ float g_hid[M_ * H2_];
__device__ __align__(16) __half g_hidp[(size_t)M_ * H2_];           // fp16 fragment-permuted
__device__ __align__(16) __half g_w2p[(size_t)VPAD2_ * H2_];        // fp16 fragment-permuted, padded

// ---------------- helpers ----------------
__device__ __forceinline__ void mma_f16(float* d, const uint32_t* a, uint32_t b0, uint32_t b1) {
    asm volatile(
        "mma.sync.aligned.m16n8k16.row.col.f32.f16.f16.f32 "
        "{%0,%1,%2,%3}, {%4,%5,%6,%7}, {%8,%9}, {%0,%1,%2,%3};\n"
        : "+f"(d[0]), "+f"(d[1]), "+f"(d[2]), "+f"(d[3])
        : "r"(a[0]), "r"(a[1]), "r"(a[2]), "r"(a[3]), "r"(b0), "r"(b1));
}

__device__ __forceinline__ float sigf(float x) {
    return __fdividef(1.f, 1.f + __expf(-x));
}
__device__ __forceinline__ float ftanh(float x) {
    float e = __expf(2.f * x);
    return 1.f - __fdividef(2.f, e + 1.f);
}

__device__ __forceinline__ uint32_t smem_u32(const void* p) {
    return (uint32_t)__cvta_generic_to_shared(p);
}

__device__ __forceinline__ void cp16(uint32_t dst, const void* src) {
    asm volatile("cp.async.cg.shared.global [%0], [%1], 16;\n"
                 :: "r"(dst), "l"(src) : "memory");
}

__device__ __forceinline__ uint32_t pack2(float lo, float hi) {
    __half2 h = __floats2half2_rn(lo, hi);
    return *(uint32_t*)&h;
}

// ---------------- K1: base gates = features @ W_hh^T + b_ih + b_hh ----------------
__global__ void base_kernel(const float* __restrict__ feat,
                            const float* __restrict__ W_hh,
                            const float* __restrict__ b_ih,
                            const float* __restrict__ b_hh,
                            float* __restrict__ base) {
    __shared__ float4 f4[H_ / 4];
    int b = blockIdx.x;
    if (threadIdx.x < H_ / 4)
        f4[threadIdx.x] = ((const float4*)(feat + (size_t)b * H_))[threadIdx.x];
    __syncthreads();
    for (int g = threadIdx.x; g < G4_; g += blockDim.x) {
        const float4* w4 = (const float4*)(W_hh + (size_t)g * H_);
        float s = 0.f;
        #pragma unroll 8
        for (int k = 0; k < H_ / 4; k++) {
            float4 w = w4[k], f = f4[k];
            s += w.x * f.x + w.y * f.y + w.z * f.z + w.w * f.w;
        }
        base[b * G4_ + g] = s + b_ih[g] + b_hh[g];
    }
}

// ---------------- generic 128x128x8 SGEMM ----------------
__global__ __launch_bounds__(256)
void sgemm_tn(const float* __restrict__ A, const float* __restrict__ Bm,
              const float* __restrict__ bias, float* __restrict__ C,
              int M, int N, int K,
              const int* __restrict__ captions, const float* __restrict__ embA) {
    __shared__ float As[8][132];
    __shared__ float Bs[8][132];
    int tid = threadIdx.x;
    int tx = tid & 15, ty = tid >> 4;
    int m0 = blockIdx.y * 128, n0 = blockIdx.x * 128;

    float acc[8][8];
    #pragma unroll
    for (int i = 0; i < 8; i++)
        #pragma unroll
        for (int j = 0; j < 8; j++) acc[i][j] = 0.f;

    int lrow = tid >> 1;
    int lkq  = tid & 1;
    const float* arow;
    if (captions) {
        int m = m0 + lrow;
        int bb = m & 31, tt = m >> 5;
        int ct = (tt == 0) ? 0 : (tt - 1);
        int tok = captions[bb * T_ + ct];
        arow = embA + (size_t)tok * K;
    } else {
        arow = A + (size_t)(m0 + lrow) * K;
    }
    const float* brow = Bm + (size_t)(n0 + lrow) * K;

    for (int k0 = 0; k0 < K; k0 += 8) {
        float4 va = *(const float4*)(arow + k0 + lkq * 4);
        float4 vb = *(const float4*)(brow + k0 + lkq * 4);
        As[lkq * 4 + 0][lrow] = va.x; As[lkq * 4 + 1][lrow] = va.y;
        As[lkq * 4 + 2][lrow] = va.z; As[lkq * 4 + 3][lrow] = va.w;
        Bs[lkq * 4 + 0][lrow] = vb.x; Bs[lkq * 4 + 1][lrow] = vb.y;
        Bs[lkq * 4 + 2][lrow] = vb.z; Bs[lkq * 4 + 3][lrow] = vb.w;
        __syncthreads();
        #pragma unroll
        for (int kk = 0; kk < 8; kk++) {
            float a[8], b[8];
            *(float4*)&a[0] = *(float4*)&As[kk][ty * 8];
            *(float4*)&a[4] = *(float4*)&As[kk][ty * 8 + 4];
            *(float4*)&b[0] = *(float4*)&Bs[kk][tx * 8];
            *(float4*)&b[4] = *(float4*)&Bs[kk][tx * 8 + 4];
            #pragma unroll
            for (int i = 0; i < 8; i++)
                #pragma unroll
                for (int j = 0; j < 8; j++) acc[i][j] += a[i] * b[j];
        }
        __syncthreads();
    }

    float bv[8];
    if (bias) {
        *(float4*)&bv[0] = *(const float4*)(bias + n0 + tx * 8);
        *(float4*)&bv[4] = *(const float4*)(bias + n0 + tx * 8 + 4);
    } else {
        #pragma unroll
        for (int j = 0; j < 8; j++) bv[j] = 0.f;
    }

    #pragma unroll
    for (int i = 0; i < 8; i++) {
        int m = m0 + ty * 8 + i;
        float* crow = C + (size_t)m * N + n0 + tx * 8;
        float o[8];
        #pragma unroll
        for (int j = 0; j < 8; j++) o[j] = acc[i][j] + bv[j];
        *(float4*)&crow[0] = *(float4*)&o[0];
        *(float4*)&crow[4] = *(float4*)&o[4];
    }
}

// ---------------- K3: LSTM scan (depth-8 prefetch) ----------------
__global__ void lstm_scan(const float* __restrict__ xg,
                          const float* __restrict__ base,
                          float* __restrict__ hs) {
    int idx = blockIdx.x * blockDim.x + threadIdx.x;
    int b = idx >> 9, h = idx & 511;
    float bi = base[b * G4_ + h];
    float bff = base[b * G4_ + H_ + h];
    float bg = base[b * G4_ + 2 * H_ + h];
    float bo = base[b * G4_ + 3 * H_ + h];

    const float* xr = xg + (size_t)b * G4_ + h;
    const size_t step = (size_t)B_ * G4_;

    float4 pf[8];
    #pragma unroll
    for (int j = 0; j < 8; j++) {
        const float* p = xr + (size_t)j * step;
        pf[j] = make_float4(p[0], p[H_], p[2 * H_], p[3 * H_]);
    }

    float c = 0.f;
    float* hp = hs + (size_t)b * H_ + h;
    #pragma unroll 8
    for (int t = 0; t < T_; t++) {
        float4 cur = pf[t & 7];
        if (t + 8 < T_) {
            const float* p = xr + (size_t)(t + 8) * step;
            pf[t & 7] = make_float4(p[0], p[H_], p[2 * H_], p[3 * H_]);
        }
        float i = sigf(cur.x + bi);
        float f = sigf(cur.y + bff);
        float g = ftanh(cur.z + bg);
        float o = sigf(cur.w + bo);
        c = f * c + i * g;
        hp[(size_t)t * B_ * H_] = o * ftanh(c);
    }
}

// ---------------- prep: permute hid (fp32) -> fp16 m16n8k16 A-fragment order ----------------
// Output uint4 index: (((mb*8 + kc)*8 + k16)*8 + tm)*32 + lane
// lane: g=lane>>2 (row), q=lane&3 (k-pair). regs: a0=[g][2q,2q+1] a1=[g+8][..] a2=[g][2q+8..] a3=[g+8][2q+8..]
__global__ void permA_kernel(const float* __restrict__ hid, uint4* __restrict__ outp) {
    int total = (M_ / 16) * (H2_ / 16) * 32;           // 262144
    for (int i = blockIdx.x * blockDim.x + threadIdx.x; i < total; i += gridDim.x * blockDim.x) {
        int lane = i & 31;
        int kt = (i >> 5) & 63;
        int mt = i >> 11;
        int g = lane >> 2, q = lane & 3;
        int r0 = mt * 16 + g, r1 = r0 + 8;
        int c0 = kt * 16 + 2 * q;
        const float* p0 = hid + (size_t)r0 * H2_ + c0;
        const float* p1 = hid + (size_t)r1 * H2_ + c0;
        float2 v0 = *(const float2*)(p0);
        float2 v1 = *(const float2*)(p1);
        float2 v2 = *(const float2*)(p0 + 8);
        float2 v3 = *(const float2*)(p1 + 8);
        uint4 o;
        o.x = pack2(v0.x, v0.y);
        o.y = pack2(v1.x, v1.y);
        o.z = pack2(v2.x, v2.y);
        o.w = pack2(v3.x, v3.y);
        int mb = mt >> 3, tm = mt & 7, kc = kt >> 3, k16 = kt & 7;
        outp[((((mb * 8 + kc) * 8 + k16) * 8 + tm) << 5) + lane] = o;
    }
}

// ---------------- prep: permute W2 (fp32) -> fp16 m16n8k16 B-fragment order ----------------
// Two n8-tiles (one n16 group) packed per uint4: {b0a, b1a, b0b, b1b}
// Output uint4 index: (((nb*8 + kc)*8 + k16)*16 + tn2)*32 + lane
__global__ void permB_kernel(const float* __restrict__ W2, uint4* __restrict__ outp) {
    int total = (VPAD2_ / 16) * (H2_ / 16) * 32;       // 3152*64*32
    for (int i = blockIdx.x * blockDim.x + threadIdx.x; i < total; i += gridDim.x * blockDim.x) {
        int lane = i & 31;
        int kt = (i >> 5) & 63;
        int nt2 = i >> 11;                              // n16 tile index
        int g = lane >> 2, q = lane & 3;
        int na = nt2 * 16 + g;
        int nb8 = na + 8;
        int c0 = kt * 16 + 2 * q;
        float2 a0 = make_float2(0.f, 0.f), a1 = a0, b0 = a0, b1 = a0;
        if (na < V_) {
            const float* p = W2 + (size_t)na * H2_ + c0;
            a0 = *(const float2*)(p);
            a1 = *(const float2*)(p + 8);
        }
        if (nb8 < V_) {
            const float* p = W2 + (size_t)nb8 * H2_ + c0;
            b0 = *(const float2*)(p);
            b1 = *(const float2*)(p + 8);
        }
        uint4 o;
        o.x = pack2(a0.x, a0.y);
        o.y = pack2(a1.x, a1.y);
        o.z = pack2(b0.x, b0.y);
        o.w = pack2(b1.x, b1.y);
        int nbk = nt2 >> 4, tn2 = nt2 & 15, kc = kt >> 3, k16 = kt & 7;
        outp[((((nbk * 8 + kc) * 8 + k16) * 16 + tn2) << 5) + lane] = o;
    }
}

// ---------------- K5: logits = hid @ W2^T + b2 (fp16 mma m16n8k16, fragment-permuted) ----------------
__global__ __launch_bounds__(512, 1)
void logits_mma(const uint4* __restrict__ Ap, const uint4* __restrict__ Bp,
                const float* __restrict__ b2, float* __restrict__ out) {
    __shared__ float b2s[BN_];
    extern __shared__ char st[];   // 2 stages x 96KB

    int tid = threadIdx.x, lane = tid & 31, warp = tid >> 5;
    int wm = warp >> 3;   // 0..1  (M)
    int wn = warp & 7;    // 0..7  (N)
    int mb = blockIdx.x, nb = blockIdx.y;

    if (tid < BN_) { int v = nb * BN_ + tid; b2s[tid] = (v < V_) ? b2[v] : 0.f; }

    const uint4* Asrc = Ap + (size_t)mb * 8 * 2048;   // 8 chunks x 2048 uint4
    const uint4* Bsrc = Bp + (size_t)nb * 8 * 4096;   // 8 chunks x 4096 uint4
    uint32_t stb = smem_u32(st);

    auto prefetch = [&](int c) {
        uint32_t d = stb + (c & 1) * ST_BYTES;
        const uint4* a4 = Asrc + (size_t)c * 2048;
        const uint4* b4 = Bsrc + (size_t)c * 4096;
        #pragma unroll
        for (int i = 0; i < 4; i++)
            cp16(d + (tid + i * 512) * 16, a4 + tid + i * 512);
        uint32_t db = d + ST_A_BYTES;
        #pragma unroll
        for (int i = 0; i < 8; i++)
            cp16(db + (tid + i * 512) * 16, b4 + tid + i * 512);
        asm volatile("cp.async.commit_group;\n" ::: "memory");
    };

    float acc[4][4][4];
    #pragma unroll
    for (int mi = 0; mi < 4; mi++)
        #pragma unroll
        for (int ni = 0; ni < 4; ni++)
            #pragma unroll
            for (int r = 0; r < 4; r++) acc[mi][ni][r] = 0.f;

    prefetch(0);
    prefetch(1);

    for (int c = 0; c < NKT_; c++) {
        if (c < NKT_ - 2)
            asm volatile("cp.async.wait_group 1;\n" ::: "memory");
        else
            asm volatile("cp.async.wait_group 0;\n" ::: "memory");
        __syncthreads();

        const uint4* SA = (const uint4*)(st + (c & 1) * ST_BYTES);     // [k16(8)][tm(8)][lane]
        const uint4* SB = SA + 2048;                                    // [k16(8)][tn2(16)][lane]

        #pragma unroll
        for (int k16 = 0; k16 < 8; k16++) {
            uint4 af[4], bf[2];
            #pragma unroll
            for (int mi = 0; mi < 4; mi++)
                af[mi] = SA[((k16 * 8 + wm * 4 + mi) << 5) + lane];
            #pragma unroll
            for (int n2 = 0; n2 < 2; n2++)
                bf[n2] = SB[((k16 * 16 + wn * 2 + n2) << 5) + lane];
            #pragma unroll
            for (int mi = 0; mi < 4; mi++)
                #pragma unroll
                for (int n2 = 0; n2 < 2; n2++) {
                    mma_f16(acc[mi][n2 * 2],     (const uint32_t*)&af[mi], bf[n2].x, bf[n2].y);
                    mma_f16(acc[mi][n2 * 2 + 1], (const uint32_t*)&af[mi], bf[n2].z, bf[n2].w);
                }
        }
        __syncthreads();
        if (c + 2 < NKT_) prefetch(c + 2);
    }

    // epilogue: m = t*B+b ; out[b][t][v]
    int g = lane >> 2, q = lane & 3;
    #pragma unroll
    for (int mi = 0; mi < 4; mi++) {
        int mA = mb * 128 + wm * 64 + mi * 16 + g;
        int mB = mA + 8;
        size_t offA = ((size_t)(mA & 31) * T_ + (size_t)(mA >> 5)) * (size_t)V_;
        size_t offB = ((size_t)(mB & 31) * T_ + (size_t)(mB >> 5)) * (size_t)V_;
        #pragma unroll
        for (int ni = 0; ni < 4; ni++) {
            int cc = wn * 32 + (ni >> 1) * 16 + (ni & 1) * 8 + q * 2;
            int n = nb * BN_ + cc;
            if (n < V_) {
                out[offA + n] = acc[mi][ni][0] + b2s[cc];
                out[offB + n] = acc[mi][ni][2] + b2s[cc];
                if (n + 1 < V_) {
                    out[offA + n + 1] = acc[mi][ni][1] + b2s[cc + 1];
                    out[offB + n + 1] = acc[mi][ni][3] + b2s[cc + 1];
                }
            }
        }
    }
}

// ---------------- launch ----------------
extern "C" void kernel_launch(void* const* d_in, const int* in_sizes, int n_in,
                              void* d_out, int out_size) {
    const float* features = (const float*)d_in[0];
    const int*   captions = (const int*)d_in[1];
    const float* emb      = (const float*)d_in[2];
    const float* W_ih     = (const float*)d_in[3];
    const float* W_hh     = (const float*)d_in[4];
    const float* b_ih     = (const float*)d_in[5];
    const float* b_hh     = (const float*)d_in[6];
    const float* W1       = (const float*)d_in[7];
    const float* b1       = (const float*)d_in[8];
    const float* W2       = (const float*)d_in[9];
    const float* b2       = (const float*)d_in[10];
    float* out = (float*)d_out;

    void *p_base, *p_xg, *p_hs, *p_hid, *p_hidp, *p_w2p;
    cudaGetSymbolAddress(&p_base, g_base);
    cudaGetSymbolAddress(&p_xg,   g_xg);
    cudaGetSymbolAddress(&p_hs,   g_hs);
    cudaGetSymbolAddress(&p_hid,  g_hid);
    cudaGetSymbolAddress(&p_hidp, g_hidp);
    cudaGetSymbolAddress(&p_w2p,  g_w2p);
    float* base = (float*)p_base;
    float* xg   = (float*)p_xg;
    float* hs   = (float*)p_hs;
    float* hid  = (float*)p_hid;

    cudaFuncSetAttribute(logits_mma, cudaFuncAttributeMaxDynamicSharedMemorySize, SMEM_DYN);

    // K0: permute + fp16-round W2
    permB_kernel<<<4096, 256>>>(W2, (uint4*)p_w2p);

    // K1: base gates
    base_kernel<<<B_, 256>>>(features, W_hh, b_ih, b_hh, base);

    // K2: x_gates = gather(emb) @ W_ih^T
    {
        dim3 grid(G4_ / 128, M_ / 128);
        sgemm_tn<<<grid, 256>>>(nullptr, W_ih, nullptr, xg,
                                M_, G4_, E_, captions, emb);
    }

    // K3: LSTM scan
    lstm_scan<<<128, 128>>>(xg, base, hs);

    // K4: hid = hs @ W1^T + b1 (fp32)
    {
        dim3 grid(H2_ / 128, M_ / 128);
        sgemm_tn<<<grid, 256>>>(hs, W1, b1, hid,
                                M_, H2_, H_, nullptr, nullptr);
    }

    // K4b: permute + fp16-round hid
    permA_kernel<<<512, 256>>>(hid, (uint4*)p_hidp);

    // K5: logits via fp16 mma with fragment-permuted operands
    {
        dim3 grid(M_ / BM_, VPAD2_ / BN_);   // (16, 197)
        logits_mma<<<grid, 512, SMEM_DYN>>>((const uint4*)p_hidp, (const uint4*)p_w2p, b2, out);
    }
}